// round 10
// baseline (speedup 1.0000x reference)
#include <cuda_runtime.h>
#include <cstdint>

// Problem constants (from reference): B=32, S=1024, D=512
#define BB 32
#define SS 1024
#define DD 512
#define DV4 (DD / 4)   // 128 float4 per row
#define TAILW 64       // s-blocks per batch sharing the tail zero-fill
#define PERT (SS / 128)  // durations per scan thread = 8

// Scratch (allocation-free; all returned to initial state by last block)
__device__ int g_ends[BB * SS];          // inclusive cumsum of clamped durations
__device__ int g_totals[BB];             // total_lengths per batch
__device__ volatile int g_flag[BB];      // per-batch "scan done" flag (0 at entry)
__device__ unsigned int g_done;          // finished-block counter (0 at entry)

__device__ __forceinline__ void st_release(volatile int* p, int v) {
    asm volatile("st.global.release.gpu.b32 [%0], %1;" :: "l"((int*)p), "r"(v) : "memory");
}
__device__ __forceinline__ int ld_acquire(volatile int* p) {
    int v;
    asm volatile("ld.global.acquire.gpu.b32 %0, [%1];" : "=r"(v) : "l"((int*)p) : "memory");
    return v;
}

// ---------------------------------------------------------------------------
// Single fused kernel. Grid (SS, BB), 128 threads.
//  * Block s==0 of each batch: computes the batch's duration scan, publishes
//    g_ends/g_totals, release-stores g_flag[b]; then scatters its own row.
//  * Other blocks: issue their x-row load, then acquire-spin on g_flag[b]
//    (wave 1 only; later waves find it set), then scatter.
//  * Last finishing block resets flags + counter for the next graph replay.
// ---------------------------------------------------------------------------
__global__ void __launch_bounds__(128)
lenreg_kernel(const float4* __restrict__ x4,
              const float*  __restrict__ dur,
              const int*    __restrict__ scale_raw,
              float4* __restrict__ out4, int T,
              float* __restrict__ len_out, int write_len)
{
    const int s   = blockIdx.x;
    const int b   = blockIdx.y;
    const int tid = threadIdx.x;

    // Scan-independent prelude: start the x read stream immediately.
    const float4 v = __ldcs(&x4[((size_t)b * SS + s) * DV4 + tid]);

    if (s == 0) {
        // ---- designated scan block for batch b ----
        const int   iv = scale_raw[0];
        const float fvs = __int_as_float(iv);
        const float af = fabsf(fvs);
        const float scale = (af >= 1e-6f && af <= 1e6f) ? fvs : (float)iv;

        const float4* db4 = (const float4*)(dur + b * SS);
        float4 a0 = __ldg(&db4[2 * tid]);
        float4 a1 = __ldg(&db4[2 * tid + 1]);
        int d[PERT];
        d[0] = (int)(a0.x * scale + 0.5f); d[1] = (int)(a0.y * scale + 0.5f);
        d[2] = (int)(a0.z * scale + 0.5f); d[3] = (int)(a0.w * scale + 0.5f);
        d[4] = (int)(a1.x * scale + 0.5f); d[5] = (int)(a1.y * scale + 0.5f);
        d[6] = (int)(a1.z * scale + 0.5f); d[7] = (int)(a1.w * scale + 0.5f);
        int tsum = 0;
        #pragma unroll
        for (int i = 0; i < PERT; ++i) { if (d[i] < 1) d[i] = 1; tsum += d[i]; }

        // inclusive scan of per-thread sums (4 warps)
        const int lane = tid & 31, warp = tid >> 5;
        int w = tsum;
        #pragma unroll
        for (int o = 1; o < 32; o <<= 1) {
            int n = __shfl_up_sync(0xffffffffu, w, o);
            if (lane >= o) w += n;
        }
        __shared__ int wsum[4];
        if (lane == 31) wsum[warp] = w;
        __syncthreads();
        int base = w - tsum, tot = 0;
        #pragma unroll
        for (int k = 0; k < 4; ++k) {
            if (k < warp) base += wsum[k];
            tot += wsum[k];
        }

        int e[PERT];
        e[0] = base + d[0];
        #pragma unroll
        for (int i = 1; i < PERT; ++i) e[i] = e[i - 1] + d[i];
        int4* eb = (int4*)(g_ends + b * SS);
        eb[2 * tid]     = make_int4(e[0], e[1], e[2], e[3]);
        eb[2 * tid + 1] = make_int4(e[4], e[5], e[6], e[7]);
        if (tid == 127) {
            g_totals[b] = tot;
            if (write_len) len_out[b] = (float)tot;
        }
        __threadfence();
        __syncthreads();
        if (tid == 127) st_release(&g_flag[b], 1);
    } else {
        // ---- spin until this batch's scan is published (wave 1 only) ----
        if (tid == 0) {
            while (ld_acquire(&g_flag[b]) == 0) __nanosleep(40);
        }
        __syncthreads();
    }

    // ---- scatter-expand this row ----
    const int end   = __ldcg(&g_ends[b * SS + s]);
    const int start = (s > 0) ? __ldcg(&g_ends[b * SS + s - 1]) : 0;

    float4* dst = out4 + ((size_t)b * T + start) * DV4 + tid;
    for (int r = start; r < end; ++r) {
        __stcs(dst, v);
        dst += DV4;
    }

    // ---- fused tail zero-fill: rows [tot, T) shared by last TAILW s-blocks
    if (s >= SS - TAILW) {
        const int tot = __ldcg(&g_totals[b]);
        const float4 z = make_float4(0.f, 0.f, 0.f, 0.f);
        for (int r = tot + (s - (SS - TAILW)); r < T; r += TAILW) {
            __stcs(out4 + ((size_t)b * T + r) * DV4 + tid, z);
        }
    }

    // ---- last block resets sync state for the next graph replay ----
    __syncthreads();
    if (tid == 0) {
        __threadfence();
        unsigned int prev = atomicAdd(&g_done, 1u);
        if (prev == (unsigned)(SS * BB - 1)) {
            #pragma unroll
            for (int i = 0; i < BB; ++i) g_flag[i] = 0;
            g_done = 0;
            __threadfence();
        }
    }
}

// ---------------------------------------------------------------------------
extern "C" void kernel_launch(void* const* d_in, const int* in_sizes, int n_in,
                              void* d_out, int out_size)
{
    const float4* x4    = (const float4*)d_in[0];   // x: (B,S,D) float32
    const float*  dur   = (const float*)d_in[1];    // durations: (B,S) float32
    const int*    scale = (const int*)d_in[2];      // duration_scale: scalar
    float* out = (float*)d_out;

    // Recover T (max total length) from out_size:
    //   out only:           out_size = B*T*D
    //   out + lengths tail: out_size = B*T*D + B
    int T, has_len;
    if (out_size % (BB * DD) == 0) {
        T = out_size / (BB * DD);
        has_len = 0;
    } else {
        T = (out_size - BB) / (BB * DD);
        has_len = 1;
    }

    lenreg_kernel<<<dim3(SS, BB), 128>>>(x4, dur, scale, (float4*)out, T,
                                         out + (size_t)BB * T * DD, has_len);
}

// round 12
// speedup vs baseline: 1.4329x; 1.4329x over previous
#include <cuda_runtime.h>
#include <cstdint>

// Problem constants (from reference): B=32, S=1024, D=512
#define BB 32
#define SS 1024
#define DD 512
#define DV4 (DD / 4)   // 128 float4 per row
#define TAILW 64       // s-blocks per batch sharing the tail zero-fill

// Scratch (allocation-free per harness rules)
__device__ int g_ends[BB * SS];   // inclusive cumsum of clamped durations, per batch
__device__ int g_totals[BB];      // total_lengths per batch

// ---------------------------------------------------------------------------
// Kernel A: per-batch duration round/clamp + inclusive scan.
// One block per batch, 256 threads, 4 durations/thread via float4.
// ---------------------------------------------------------------------------
__global__ void __launch_bounds__(256)
durscan_kernel(const float* __restrict__ durations, const int* __restrict__ scale_raw,
               float* __restrict__ len_out, int write_len)
{
    const int b   = blockIdx.x;
    const int tid = threadIdx.x;
    const int lane = tid & 31;
    const int warp = tid >> 5;

    // duration_scale dtype is ambiguous (python int 1 vs float 1.0).
    // Interpret the raw word as float if in a sane range, else as int.
    const int   iv = scale_raw[0];
    const float fv = __int_as_float(iv);
    const float af = fabsf(fv);
    const float scale = (af >= 1e-6f && af <= 1e6f) ? fv : (float)iv;

    // 4 consecutive durations per thread
    const float4 dv = __ldg(((const float4*)(durations + b * SS)) + tid);
    int d0 = (int)(dv.x * scale + 0.5f); if (d0 < 1) d0 = 1;
    int d1 = (int)(dv.y * scale + 0.5f); if (d1 < 1) d1 = 1;
    int d2 = (int)(dv.z * scale + 0.5f); if (d2 < 1) d2 = 1;
    int d3 = (int)(dv.w * scale + 0.5f); if (d3 < 1) d3 = 1;
    const int tsum = d0 + d1 + d2 + d3;

    // Inclusive scan of per-thread sums: warp shuffle + 8 warp partials.
    int v = tsum;
    #pragma unroll
    for (int o = 1; o < 32; o <<= 1) {
        int n = __shfl_up_sync(0xffffffffu, v, o);
        if (lane >= o) v += n;
    }
    __shared__ int wsum[8];
    if (lane == 31) wsum[warp] = v;
    __syncthreads();
    int wbase = 0, tot = 0;
    #pragma unroll
    for (int w = 0; w < 8; ++w) {
        if (w < warp) wbase += wsum[w];
        tot += wsum[w];
    }
    const int base = wbase + v - tsum;   // exclusive prefix for this thread

    int4 e;
    e.x = base + d0;
    e.y = e.x + d1;
    e.z = e.y + d2;
    e.w = e.z + d3;
    ((int4*)(g_ends + b * SS))[tid] = e;

    if (tid == 255) {
        g_totals[b] = tot;
        if (write_len) len_out[b] = (float)tot;
    }
}

// ---------------------------------------------------------------------------
// Kernel B: scatter-expand + fused tail zero-fill.
// One 128-thread block per (s, b) source row. Each thread holds one float4 of
// x[b][s] in a register and streams it to output rows [start, end).
// The last TAILW s-blocks of each batch additionally zero-fill the masked
// tail rows [tot, T) in a strided, balanced fashion (output is 0xAA-poisoned).
// ---------------------------------------------------------------------------
__global__ void __launch_bounds__(128)
scatter_kernel(const float4* __restrict__ x4, float4* __restrict__ out4, int T)
{
    const int s = blockIdx.x;
    const int b = blockIdx.y;

    const int end   = g_ends[b * SS + s];
    const int start = (s > 0) ? g_ends[b * SS + s - 1] : 0;

    const float4 v = __ldcs(&x4[((size_t)b * SS + s) * DV4 + threadIdx.x]);

    float4* dst = out4 + ((size_t)b * T + start) * DV4 + threadIdx.x;
    for (int r = start; r < end; ++r) {
        __stcs(dst, v);
        dst += DV4;
    }

    // Fused tail zero-fill: rows [tot, T) shared across the last TAILW blocks.
    if (s >= SS - TAILW) {
        const int tot = g_totals[b];
        const float4 z = make_float4(0.f, 0.f, 0.f, 0.f);
        for (int r = tot + (s - (SS - TAILW)); r < T; r += TAILW) {
            __stcs(out4 + ((size_t)b * T + r) * DV4 + threadIdx.x, z);
        }
    }
}

// ---------------------------------------------------------------------------
extern "C" void kernel_launch(void* const* d_in, const int* in_sizes, int n_in,
                              void* d_out, int out_size)
{
    const float4* x4    = (const float4*)d_in[0];   // x: (B,S,D) float32
    const float*  dur   = (const float*)d_in[1];    // durations: (B,S) float32
    const int*    scale = (const int*)d_in[2];      // duration_scale: scalar
    float* out = (float*)d_out;

    // Recover T (max total length) from out_size:
    //   out only:           out_size = B*T*D
    //   out + lengths tail: out_size = B*T*D + B
    int T, has_len;
    if (out_size % (BB * DD) == 0) {
        T = out_size / (BB * DD);
        has_len = 0;
    } else {
        T = (out_size - BB) / (BB * DD);
        has_len = 1;
    }

    durscan_kernel<<<BB, 256>>>(dur, scale, out + (size_t)BB * T * DD, has_len);
    scatter_kernel<<<dim3(SS, BB), 128>>>(x4, (float4*)out, T);
}